// round 14
// baseline (speedup 1.0000x reference)
#include <cuda_runtime.h>
#include <cuda_fp16.h>
#include <cstdint>
#include <math.h>

// ---------------- problem constants ----------------
#define HEADS 2
#define DHEAD 32
#define HW    40
#define HP    42
#define NPIX  (HP*HP)
#define NH    20
#define NWIN  400
#define NTOK  16
#define LTOT  6400
#define SCALE 0.17677669529663687f
#define QSCL  (0.17677669529663687f * 1.4426950408889634f)  // SCALE * log2(e)
#define SBIAS (-5.0f)   // exponent bias: p' = 2^(s-5), cancels in o = sum(p'v)/sum(p')

// flash work decomposition (persistent balanced schedule)
#define KT        128         // keys per unit (two 64-key halves per sync)
#define UPR       50          // units per row-group (6400/128)
#define NRG       100         // row-groups: 2 heads x 50 q-tiles of 128 rows
#define UTOT      (NRG*UPR)   // 5000
#define G_BLOCKS  296         // exactly 2 blocks/SM x 148 SMs -> uniform 16 warps/SM
#define NSLOT     4           // max blocks intersecting one row-group
// smem byte offsets within one buffer (unit = 128 keys)
#define B_KH   0              // 128 keys x 80B (64B fp16 data + 16 pad)
#define B_KL   10240
#define B_VTH  20480          // 32 dims x 272B (256B fp16 data + 16 pad)
#define B_VTL  29184
#define BUFB   37888
#define NBUF   3
#define SMEM_FL (NBUF*BUFB)   // 113664 bytes dynamic; 2 blocks/SM fits 228KB SM budget

// ---------------- scratch ----------------
__device__ float g_qx[NPIX*64];
__device__ float g_kx[NPIX*64];
__device__ float g_vx[NPIX*64];
__device__ float g_qz[NPIX*64];
__device__ float g_kz[NPIX*64];
__device__ float g_qg[HEADS*LTOT*DHEAD];            // local-attn out == global QKV (fp32)
__device__ __align__(256) unsigned short g_qs[HEADS*LTOT*32];      // fp16(q*QSCL) hi only
__device__ __align__(256) unsigned short g_ks[HEADS*LTOT*64];      // [kh32 | kl32] fp16
__device__ __align__(256) unsigned short g_vt[HEADS*2*DHEAD*LTOT]; // [h][split][d][key] fp16
__device__ float g_po[NRG*NSLOT*128*DHEAD];         // partial unnormalized O per (rg, slot)
__device__ float g_pl[NRG*NSLOT*128];               // partial expsum per (rg, slot)

// ---------------- helpers ----------------
static __device__ __forceinline__ uint32_t smem_u32(const void* p) {
    uint32_t a;
    asm("{ .reg .u64 t; cvta.to.shared.u64 t, %1; cvt.u32.u64 %0, t; }" : "=r"(a) : "l"(p));
    return a;
}
static __device__ __forceinline__ uint32_t packh(float lo, float hi) {
    uint32_t r; asm("cvt.rn.satfinite.f16x2.f32 %0, %1, %2;" : "=r"(r) : "f"(hi), "f"(lo)); return r;
}
static __device__ __forceinline__ uint32_t ex2h2(uint32_t a) {
    uint32_t r; asm("ex2.approx.f16x2 %0, %1;" : "=r"(r) : "r"(a)); return r;
}
// mma.sync m16n8k16 fp16 with fp32 accum (sm_80+ baseline PTX; Blackwell tensor pipe)
static __device__ __forceinline__ void mma_f16(float* d, const uint32_t* a, uint32_t b0, uint32_t b1) {
    asm volatile("mma.sync.aligned.m16n8k16.row.col.f32.f16.f16.f32 "
        "{%0,%1,%2,%3}, {%4,%5,%6,%7}, {%8,%9}, {%0,%1,%2,%3};"
        : "+f"(d[0]), "+f"(d[1]), "+f"(d[2]), "+f"(d[3])
        : "r"(a[0]), "r"(a[1]), "r"(a[2]), "r"(a[3]), "r"(b0), "r"(b1));
}
// ldmatrix x4: one issue slot loads four 8x8 b16 fragments
static __device__ __forceinline__ void ldm_x4(uint32_t* r, uint32_t addr) {
    asm volatile("ldmatrix.sync.aligned.m8n8.x4.shared.b16 {%0,%1,%2,%3}, [%4];"
        : "=r"(r[0]), "=r"(r[1]), "=r"(r[2]), "=r"(r[3]) : "r"(addr));
}
static __device__ __forceinline__ void cp_async16(uint32_t dst, const void* src) {
    asm volatile("cp.async.cg.shared.global [%0], [%1], 16;" :: "r"(dst), "l"(src));
}
#define CP_COMMIT() asm volatile("cp.async.commit_group;" ::: "memory")

static __device__ __forceinline__ int reflect40(int v) {
    return v < 0 ? -v : (v > 39 ? 78 - v : v);
}

// ---------------- kernel 1: conv1x1 projections with reflect pad ----------------
// grid = (42, 4): row yp, pixel chunk of <=11. block = 320 (one thread per out channel)
__global__ void proj_kernel(const float* __restrict__ x, const float* __restrict__ z,
                            const float* __restrict__ Wx, const float* __restrict__ bx,
                            const float* __restrict__ Wz, const float* __restrict__ bz) {
    __shared__ __align__(16) float xs[11*68];
    __shared__ __align__(16) float zs[11*68];
    int yp = blockIdx.x;
    int x0 = blockIdx.y * 11;
    int x1 = x0 + 11; if (x1 > HP) x1 = HP;
    int npx = x1 - x0;
    int ys = reflect40(yp - 1);
    for (int idx = threadIdx.x; idx < 11*64; idx += blockDim.x) {
        int c = idx / 11, lx = idx % 11;
        if (lx < npx) {
            int xsrc = reflect40(x0 + lx - 1);
            int src = c*1600 + ys*HW + xsrc;
            xs[lx*68 + c] = x[src];
            zs[lx*68 + c] = z[src];
        }
    }
    __syncthreads();
    int oc = threadIdx.x;
    const float* wrow; float bias; float* dst; int cout; const float* sm;
    if (oc < 192) {
        wrow = Wx + oc*64; bias = bx[oc];
        int t = oc >> 6; cout = oc & 63;
        dst = (t == 0) ? g_qx : (t == 1 ? g_kx : g_vx);
        sm = xs;
    } else {
        int ozc = oc - 192;
        wrow = Wz + ozc*64; bias = bz[ozc];
        cout = ozc & 63;
        dst = (ozc < 64) ? g_qz : g_kz;
        sm = zs;
    }
    float4 wr[16];
    #pragma unroll
    for (int i = 0; i < 16; i++) wr[i] = ((const float4*)wrow)[i];
    for (int lx = 0; lx < npx; lx++) {
        float acc = bias;
        #pragma unroll
        for (int i = 0; i < 16; i++) {
            float4 v = *(const float4*)(sm + lx*68 + i*4);
            acc += wr[i].x*v.x + wr[i].y*v.y + wr[i].z*v.z + wr[i].w*v.w;
        }
        dst[(yp*HP + x0 + lx)*64 + cout] = acc;
    }
}

// ---------------- kernel 2: local 16x16 window attention ----------------
// grid = (400, 2) = (window, head), block = 256 = (i,j)
__global__ void local_attn_kernel(const float* __restrict__ pbeta_p) {
    __shared__ __align__(16) float sq[16*36], sk[16*36], sv[16*36], sqz[16*36], skz[16*36];
    __shared__ float sA[16*17];
    int win = blockIdx.x, h = blockIdx.y;
    int sy = (win / NH) * 2, sx = (win % NH) * 2;
    int tid = threadIdx.x;
    float* tiles[5] = {sq, sk, sv, sqz, skz};
    const float* gsrc[5] = {g_qx, g_kx, g_vx, g_qz, g_kz};
    for (int idx = tid; idx < 640; idx += 256) {
        int t = idx >> 7, rem = idx & 127, tok = rem >> 3, f4 = rem & 7;
        int ty = tok >> 2, tx = tok & 3;
        int pix = (sy + ty)*HP + (sx + tx);
        float4 v = *(const float4*)(gsrc[t] + pix*64 + h*DHEAD + f4*4);
        *(float4*)(tiles[t] + tok*36 + f4*4) = v;
    }
    __syncthreads();
    float pb = *pbeta_p;
    float beta = fmaxf(pb, 0.f) + log1pf(__expf(-fabsf(pb))) + 1e-6f;
    int i = tid >> 4, j = tid & 15;
    float dx = 0.f, dz = 0.f;
    {
        const float4* qr  = (const float4*)(sq  + i*36);
        const float4* kr  = (const float4*)(sk  + j*36);
        const float4* qzr = (const float4*)(sqz + i*36);
        const float4* kzr = (const float4*)(skz + j*36);
        #pragma unroll
        for (int d4 = 0; d4 < 8; d4++) {
            float4 a = qr[d4],  b = kr[d4];
            float4 c = qzr[d4], e = kzr[d4];
            dx += a.x*b.x + a.y*b.y + a.z*b.z + a.w*b.w;
            dz += c.x*e.x + c.y*e.y + c.z*e.z + c.w*e.w;
        }
    }
    float s = SCALE * (dx + beta*dz);
    float mx = s;
    #pragma unroll
    for (int off = 8; off; off >>= 1) mx = fmaxf(mx, __shfl_xor_sync(0xffffffffu, mx, off, 16));
    float p = __expf(s - mx);
    float sum = p;
    #pragma unroll
    for (int off = 8; off; off >>= 1) sum += __shfl_xor_sync(0xffffffffu, sum, off, 16);
    sA[i*17 + j] = p / sum;
    __syncthreads();
    #pragma unroll
    for (int pair = 0; pair < 2; pair++) {
        int idx = tid + pair*256;
        int ii = idx >> 5, dd = idx & 31;
        float acc = 0.f;
        #pragma unroll
        for (int jj = 0; jj < 16; jj++) acc += sA[ii*17+jj] * sv[jj*36+dd];
        g_qg[h*(LTOT*DHEAD) + (win*16 + ii)*DHEAD + dd] = acc;
    }
}

// ---------------- kernel 2.5: fp32 -> fp16 hi/lo splits (Q scaled hi-only, K, V^T) ----
// grid = 100 blocks x 128 threads; block handles 128 consecutive rows (head-aligned)
__global__ void prep_kernel() {
    __shared__ __align__(16) unsigned short vs[2][32][128];   // [split][d][key-local]
    const int tid = threadIdx.x;
    const int h = blockIdx.x / 50;
    const int r0 = (blockIdx.x * 128) % LTOT;
    const int g = blockIdx.x * 128 + tid;

    float qv[32];
    {
        const float4* qp = (const float4*)(g_qg + (size_t)g*DHEAD);
        #pragma unroll
        for (int i = 0; i < 8; i++) {
            float4 v = qp[i];
            qv[4*i] = v.x; qv[4*i+1] = v.y; qv[4*i+2] = v.z; qv[4*i+3] = v.w;
        }
    }
    uint32_t qu[16], ku[32];
    #pragma unroll
    for (int j = 0; j < 16; j++) {
        float a = qv[2*j], b = qv[2*j+1];
        __half ah = __float2half_rn(a), bh = __float2half_rn(b);
        uint32_t khp = ((uint32_t)__half_as_ushort(bh) << 16) | __half_as_ushort(ah);
        __half al = __float2half_rn(a - __half2float(ah));
        __half bl = __float2half_rn(b - __half2float(bh));
        uint32_t klp = ((uint32_t)__half_as_ushort(bl) << 16) | __half_as_ushort(al);
        ku[j] = khp; ku[16+j] = klp;
        vs[0][2*j][tid]   = __half_as_ushort(ah);
        vs[0][2*j+1][tid] = __half_as_ushort(bh);
        vs[1][2*j][tid]   = __half_as_ushort(al);
        vs[1][2*j+1][tid] = __half_as_ushort(bl);
        qu[j] = packh(a * QSCL, b * QSCL);
    }
    {
        float4* qd = (float4*)(g_qs + (size_t)g*32);
        float4* kd = (float4*)(g_ks + (size_t)g*64);
        const float4* qs4 = (const float4*)qu;
        const float4* ks4 = (const float4*)ku;
        #pragma unroll
        for (int i = 0; i < 4; i++) qd[i] = qs4[i];
        #pragma unroll
        for (int i = 0; i < 8; i++) kd[i] = ks4[i];
    }
    __syncthreads();
    // coalesced transposed V writes: [h][sp][d][r0 + 0..127]
    #pragma unroll
    for (int sp = 0; sp < 2; sp++) {
        #pragma unroll
        for (int j = 0; j < 4; j++) {
            int idx = tid + j*128;            // 0..511
            int d = idx >> 4, c = idx & 15;
            float4 v = *(const float4*)&vs[sp][d][c*8];
            *(float4*)(g_vt + ((size_t)((h*2+sp)*DHEAD + d))*LTOT + r0 + c*8) = v;
        }
    }
}

// ---------------- kernel 3: persistent flash attention, fp16 2+2 GEMM scheme ----------------
// grid = 296 blocks x 256 thr (8 warps x 16 rows). Work = 5000 units of 128 keys,
// contiguous split; each unit processed as two 64-key halves behind ONE barrier.
__global__ void __launch_bounds__(256, 2) flashmma_kernel() {
    extern __shared__ __align__(16) char smem[];
    const int tid = threadIdx.x, w = tid >> 5, lane = tid & 31;
    const int tg = lane >> 2, tc = lane & 3;            // groupID, threadInGroup
    const int b = blockIdx.x;
    const int ustart = (b * UTOT) / G_BLOCKS;
    const int uend = ((b + 1) * UTOT) / G_BLOCKS;
    const uint32_t sbase = smem_u32(smem);
    // per-thread ldmatrix row addresses (relative to buffer base)
    const uint32_t lmK = (uint32_t)((lane & 7)*80  + (lane >> 3)*16);
    const uint32_t lmV = (uint32_t)((lane & 7)*272 + (lane >> 3)*16);
    // constant B-fragment for the ones column (n==0): row sums land in D[:,0]
    const uint32_t ones = (tg == 0) ? 0x3C003C00u : 0u;

    // ---- cooperative tile load for global unit u (128 keys) into buffer slot ----
    auto load_unit = [&](int u, int slot) {
        const int gg = u / UPR, hh = gg / 50, kt = u % UPR;
        uint32_t db = sbase + slot*BUFB;
        const char* kg = (const char*)(g_ks + ((size_t)hh*LTOT + kt*KT)*64);
        #pragma unroll
        for (int j = 0; j < 4; j++) {
            int i = tid + j*256;                        // 0..1023
            int r = i >> 3, half = (i >> 2) & 1, c = i & 3;
            cp_async16(db + (half ? B_KL : B_KH) + r*80 + c*16,
                       kg + r*128 + half*64 + c*16);
        }
        #pragma unroll
        for (int j = 0; j < 4; j++) {
            int i = tid + j*256;                        // sp2 x d32 x kg16
            int vsp = i >> 9, rem = i & 511, d = rem >> 4, kgi = rem & 15;
            const char* src = (const char*)(g_vt + ((size_t)(hh*2+vsp)*DHEAD + d)*LTOT + kt*KT) + kgi*16;
            cp_async16(db + (vsp ? B_VTL : B_VTH) + d*272 + kgi*16, src);
        }
        CP_COMMIT();
    };

    load_unit(ustart, 0);
    if (ustart + 1 < uend) load_unit(ustart + 1, 1);

    float oacc[4][4];
    float lacc[4];
    uint32_t qh[2][4];
    int cg = -1;

    auto flush = [&](int g) {
        const int b_first = (g*UPR*G_BLOCKS + G_BLOCKS - 1) / UTOT;
        const int slot = b - b_first;
        const int rowa = w*16 + tg, rowb = rowa + 8;
        const int pbase = (g*NSLOT + slot)*128;
        if (tc == 0) { g_pl[pbase + rowa] = lacc[0]; g_pl[pbase + rowb] = lacc[2]; }
        float2* pa  = (float2*)(g_po + ((size_t)(pbase + rowa))*DHEAD);
        float2* pbv = (float2*)(g_po + ((size_t)(pbase + rowb))*DHEAD);
        #pragma unroll
        for (int dt = 0; dt < 4; dt++) {
            pa [dt*4 + tc] = make_float2(oacc[dt][0], oacc[dt][1]);
            pbv[dt*4 + tc] = make_float2(oacc[dt][2], oacc[dt][3]);
        }
    };

    for (int u = ustart; u < uend; u++) {
        const int g = u / UPR;
        if (g != cg) {
            if (cg >= 0) flush(cg);
            cg = g;
            const int h = g / 50, qt = g % 50;
            const uint32_t* qb = (const uint32_t*)g_qs + ((size_t)h*LTOT + qt*128 + w*16)*16;
            #pragma unroll
            for (int ks = 0; ks < 2; ks++) {
                int ca = ks*8 + tc;
                qh[ks][0] = qb[tg*16     + ca];
                qh[ks][1] = qb[(tg+8)*16 + ca];
                qh[ks][2] = qb[tg*16     + ca + 4];
                qh[ks][3] = qb[(tg+8)*16 + ca + 4];
            }
            #pragma unroll
            for (int i = 0; i < 4; i++) {
                lacc[i] = 0.f;
                #pragma unroll
                for (int j = 0; j < 4; j++) oacc[i][j] = 0.f;
            }
        }

        if (u + 1 < uend) asm volatile("cp.async.wait_group 1;" ::: "memory");
        else              asm volatile("cp.async.wait_group 0;" ::: "memory");
        __syncthreads();

        const uint32_t kb = sbase + ((u - ustart) % NBUF)*BUFB;

        // ---- two 64-key halves behind one barrier ----
        #pragma unroll
        for (int s2 = 0; s2 < 2; s2++) {
            const uint32_t kK = kb + s2*5120 + lmK;   // 64 rows x 80B per half
            const uint32_t kV = kb + s2*128 + lmV;    // 64-key column slice per half

            // S = Q K^T (2 fp16 GEMM halves), accumulator pre-biased by SBIAS
            float sacc[8][4];
            #pragma unroll
            for (int nt = 0; nt < 8; nt++) {
                sacc[nt][0] = sacc[nt][1] = sacc[nt][2] = sacc[nt][3] = SBIAS;
                uint32_t bh[4], bl[4];
                ldm_x4(bh, kK + B_KH + nt*640);
                ldm_x4(bl, kK + B_KL + nt*640);
                mma_f16(sacc[nt], qh[0], bh[0], bh[1]);
                mma_f16(sacc[nt], qh[1], bh[2], bh[3]);
                mma_f16(sacc[nt], qh[0], bl[0], bl[1]);
                mma_f16(sacc[nt], qh[1], bl[2], bl[3]);
            }

            // epilogue: p' = 2^(s-5) in f16x2; row-sum via ones-column GEMM
            uint32_t pha[4][4];
            #pragma unroll
            for (int kt2 = 0; kt2 < 4; kt2++) {
                pha[kt2][0] = ex2h2(packh(sacc[2*kt2][0],   sacc[2*kt2][1]));
                pha[kt2][1] = ex2h2(packh(sacc[2*kt2][2],   sacc[2*kt2][3]));
                pha[kt2][2] = ex2h2(packh(sacc[2*kt2+1][0], sacc[2*kt2+1][1]));
                pha[kt2][3] = ex2h2(packh(sacc[2*kt2+1][2], sacc[2*kt2+1][3]));
            }
            #pragma unroll
            for (int kt2 = 0; kt2 < 4; kt2++)
                mma_f16(lacc, pha[kt2], ones, ones);

            // O += P V (2 fp16 GEMM halves)
            #pragma unroll
            for (int dt = 0; dt < 4; dt++) {
                uint32_t vh[8], vl[8];
                ldm_x4(vh,     kV + B_VTH + dt*2176);
                ldm_x4(vh + 4, kV + B_VTH + dt*2176 + 64);
                ldm_x4(vl,     kV + B_VTL + dt*2176);
                ldm_x4(vl + 4, kV + B_VTL + dt*2176 + 64);
                #pragma unroll
                for (int kt2 = 0; kt2 < 4; kt2++) {
                    mma_f16(oacc[dt], pha[kt2], vh[2*kt2], vh[2*kt2+1]);
                    mma_f16(oacc[dt], pha[kt2], vl[2*kt2], vl[2*kt2+1]);
                }
            }
        }

        // ---- prefetch unit u+2 into the buffer freed two iterations ago ----
        if (u + 2 < uend) load_unit(u + 2, (u - ustart + 2) % NBUF);
    }
    flush(cg);
}

// ---------------- kernel 4: fused slot-merge + overlap-average + proj conv + residual ----
// grid = 1600 (pixels), block = 64 (channels). Each g_po row-element is consumed
// exactly once across the grid, so inlining the merge duplicates no work.
__global__ void final_kernel(const float* __restrict__ x,
                             const float* __restrict__ Wp, const float* __restrict__ bp,
                             const float* __restrict__ pa_p, float* __restrict__ out) {
    __shared__ __align__(16) float sg[64];
    int p = blockIdx.x;
    int y = p / HW, xq = p % HW;
    int yp = y + 1, xp = xq + 1;
    int c = threadIdx.x;
    int h = c >> 5, dd = c & 31;
    int sylo = yp - 3; if (sylo < 0) sylo = 0; sylo += (sylo & 1);
    int syhi = yp > 38 ? 38 : yp;  syhi -= (syhi & 1);
    int sxlo = xp - 3; if (sxlo < 0) sxlo = 0; sxlo += (sxlo & 1);
    int sxhi = xp > 38 ? 38 : xp;  sxhi -= (sxhi & 1);
    float acc = 0.f; int cnt = 0;
    for (int sy = sylo; sy <= syhi; sy += 2)
        for (int sx = sxlo; sx <= sxhi; sx += 2) {
            int ty = yp - sy, tx = xp - sx;
            int lw = ((sy >> 1)*NH + (sx >> 1))*NTOK + ty*4 + tx;
            int qt = lw >> 7, rowlocal = lw & 127;
            int g = h*50 + qt;
            int b_first = (g*UPR*G_BLOCKS + G_BLOCKS - 1) / UTOT;
            int b_last  = ((g+1)*UPR*G_BLOCKS - 1) / UTOT;
            int ns = b_last - b_first + 1;
            float l = 0.f, v = 0.f;
            for (int s = 0; s < ns; s++) {
                int pb_ = (g*NSLOT + s)*128 + rowlocal;
                l += g_pl[pb_];
                v += g_po[(size_t)pb_*DHEAD + dd];
            }
            acc += __fdividef(v, l);
            cnt++;
        }
    sg[c] = acc / ((float)cnt + 1e-6f);
    __syncthreads();
    float a = 2.f / (1.f + __expf(-(*pa_p)));
    float pr = bp[c];
    const float4* wrow = (const float4*)(Wp + c*64);
    #pragma unroll
    for (int i = 0; i < 16; i++) {
        float4 w = wrow[i];
        float4 g = *(const float4*)(sg + i*4);
        pr += w.x*g.x + w.y*g.y + w.z*g.z + w.w*g.w;
    }
    int oi = c*1600 + y*HW + xq;
    out[oi] = x[oi] + a*pr;
}

// ---------------- launcher ----------------
extern "C" void kernel_launch(void* const* d_in, const int* in_sizes, int n_in,
                              void* d_out, int out_size) {
    (void)in_sizes; (void)n_in; (void)out_size;
    const float* x     = (const float*)d_in[0];
    const float* z     = (const float*)d_in[1];
    const float* Wqkv  = (const float*)d_in[2];
    const float* bqkv  = (const float*)d_in[3];
    const float* Wqkz  = (const float*)d_in[4];
    const float* bqkz  = (const float*)d_in[5];
    const float* Wproj = (const float*)d_in[6];
    const float* bproj = (const float*)d_in[7];
    const float* pa    = (const float*)d_in[8];
    const float* pbeta = (const float*)d_in[9];
    float* out = (float*)d_out;

    cudaFuncSetAttribute(flashmma_kernel, cudaFuncAttributeMaxDynamicSharedMemorySize, SMEM_FL);

    proj_kernel<<<dim3(HP, 4), 320>>>(x, z, Wqkv, bqkv, Wqkz, bqkz);
    local_attn_kernel<<<dim3(NWIN, HEADS), 256>>>(pbeta);
    prep_kernel<<<100, 128>>>();
    flashmma_kernel<<<G_BLOCKS, 256, SMEM_FL>>>();
    final_kernel<<<HW*HW, 64>>>(x, Wproj, bproj, pa, out);
}

// round 15
// speedup vs baseline: 1.3516x; 1.3516x over previous
#include <cuda_runtime.h>
#include <cuda_fp16.h>
#include <cstdint>
#include <math.h>

// ---------------- problem constants ----------------
#define HEADS 2
#define DHEAD 32
#define HW    40
#define HP    42
#define NPIX  (HP*HP)
#define NH    20
#define NWIN  400
#define NTOK  16
#define LTOT  6400
#define SCALE 0.17677669529663687f
#define QSCL  (0.17677669529663687f * 1.4426950408889634f)  // SCALE * log2(e)
#define SBIAS (-5.0f)   // exponent bias: p' = 2^(s-5), cancels in o = sum(p'v)/sum(p')

// flash work decomposition (persistent balanced schedule)
#define KT        128         // keys per unit (two 64-key halves per sync)
#define UPR       50          // units per row-group (6400/128)
#define NRG       100         // row-groups: 2 heads x 50 q-tiles of 128 rows
#define UTOT      (NRG*UPR)   // 5000
#define G_BLOCKS  296         // exactly 2 blocks/SM x 148 SMs -> uniform 16 warps/SM
#define NSLOT     4           // max blocks intersecting one row-group
// smem byte offsets within one buffer (unit = 128 keys, hi-splits only)
#define B_KH   0              // 128 keys x 80B (64B fp16 data + 16 pad)
#define B_VTH  10240          // 32 dims x 272B (256B fp16 data + 16 pad)
#define BUFB   18944
#define NBUF   3
#define SMEM_FL (NBUF*BUFB)   // 56832 bytes dynamic

// ---------------- scratch ----------------
__device__ float g_qx[NPIX*64];
__device__ float g_kx[NPIX*64];
__device__ float g_vx[NPIX*64];
__device__ float g_qz[NPIX*64];
__device__ float g_kz[NPIX*64];
__device__ float g_qg[HEADS*LTOT*DHEAD];            // local-attn out == global QKV (fp32)
__device__ __align__(256) unsigned short g_qs[HEADS*LTOT*32];   // fp16(q*QSCL)
__device__ __align__(256) unsigned short g_ks[HEADS*LTOT*32];   // fp16(k)
__device__ __align__(256) unsigned short g_vt[HEADS*DHEAD*LTOT];// [h][d][key] fp16(v)
__device__ float g_po[NRG*NSLOT*128*DHEAD];         // partial unnormalized O per (rg, slot)
__device__ float g_pl[NRG*NSLOT*128];               // partial expsum per (rg, slot)

// ---------------- helpers ----------------
static __device__ __forceinline__ uint32_t smem_u32(const void* p) {
    uint32_t a;
    asm("{ .reg .u64 t; cvta.to.shared.u64 t, %1; cvt.u32.u64 %0, t; }" : "=r"(a) : "l"(p));
    return a;
}
static __device__ __forceinline__ uint32_t packh(float lo, float hi) {
    uint32_t r; asm("cvt.rn.satfinite.f16x2.f32 %0, %1, %2;" : "=r"(r) : "f"(hi), "f"(lo)); return r;
}
static __device__ __forceinline__ uint32_t ex2h2(uint32_t a) {
    uint32_t r; asm("ex2.approx.f16x2 %0, %1;" : "=r"(r) : "r"(a)); return r;
}
// mma.sync m16n8k16 fp16 with fp32 accum (sm_80+ baseline PTX; Blackwell tensor pipe)
static __device__ __forceinline__ void mma_f16(float* d, const uint32_t* a, uint32_t b0, uint32_t b1) {
    asm volatile("mma.sync.aligned.m16n8k16.row.col.f32.f16.f16.f32 "
        "{%0,%1,%2,%3}, {%4,%5,%6,%7}, {%8,%9}, {%0,%1,%2,%3};"
        : "+f"(d[0]), "+f"(d[1]), "+f"(d[2]), "+f"(d[3])
        : "r"(a[0]), "r"(a[1]), "r"(a[2]), "r"(a[3]), "r"(b0), "r"(b1));
}
// ldmatrix x4: one issue slot loads four 8x8 b16 fragments
static __device__ __forceinline__ void ldm_x4(uint32_t* r, uint32_t addr) {
    asm volatile("ldmatrix.sync.aligned.m8n8.x4.shared.b16 {%0,%1,%2,%3}, [%4];"
        : "=r"(r[0]), "=r"(r[1]), "=r"(r[2]), "=r"(r[3]) : "r"(addr));
}
static __device__ __forceinline__ void cp_async16(uint32_t dst, const void* src) {
    asm volatile("cp.async.cg.shared.global [%0], [%1], 16;" :: "r"(dst), "l"(src));
}
#define CP_COMMIT() asm volatile("cp.async.commit_group;" ::: "memory")

static __device__ __forceinline__ int reflect40(int v) {
    return v < 0 ? -v : (v > 39 ? 78 - v : v);
}

// ---------------- kernel 1: conv1x1 projections with reflect pad ----------------
// grid = (42, 4): row yp, pixel chunk of <=11. block = 320 (one thread per out channel)
__global__ void proj_kernel(const float* __restrict__ x, const float* __restrict__ z,
                            const float* __restrict__ Wx, const float* __restrict__ bx,
                            const float* __restrict__ Wz, const float* __restrict__ bz) {
    __shared__ __align__(16) float xs[11*68];
    __shared__ __align__(16) float zs[11*68];
    int yp = blockIdx.x;
    int x0 = blockIdx.y * 11;
    int x1 = x0 + 11; if (x1 > HP) x1 = HP;
    int npx = x1 - x0;
    int ys = reflect40(yp - 1);
    for (int idx = threadIdx.x; idx < 11*64; idx += blockDim.x) {
        int c = idx / 11, lx = idx % 11;
        if (lx < npx) {
            int xsrc = reflect40(x0 + lx - 1);
            int src = c*1600 + ys*HW + xsrc;
            xs[lx*68 + c] = x[src];
            zs[lx*68 + c] = z[src];
        }
    }
    __syncthreads();
    int oc = threadIdx.x;
    const float* wrow; float bias; float* dst; int cout; const float* sm;
    if (oc < 192) {
        wrow = Wx + oc*64; bias = bx[oc];
        int t = oc >> 6; cout = oc & 63;
        dst = (t == 0) ? g_qx : (t == 1 ? g_kx : g_vx);
        sm = xs;
    } else {
        int ozc = oc - 192;
        wrow = Wz + ozc*64; bias = bz[ozc];
        cout = ozc & 63;
        dst = (ozc < 64) ? g_qz : g_kz;
        sm = zs;
    }
    float4 wr[16];
    #pragma unroll
    for (int i = 0; i < 16; i++) wr[i] = ((const float4*)wrow)[i];
    for (int lx = 0; lx < npx; lx++) {
        float acc = bias;
        #pragma unroll
        for (int i = 0; i < 16; i++) {
            float4 v = *(const float4*)(sm + lx*68 + i*4);
            acc += wr[i].x*v.x + wr[i].y*v.y + wr[i].z*v.z + wr[i].w*v.w;
        }
        dst[(yp*HP + x0 + lx)*64 + cout] = acc;
    }
}

// ---------------- kernel 2: local 16x16 window attention ----------------
// grid = (400, 2) = (window, head), block = 256 = (i,j)
__global__ void local_attn_kernel(const float* __restrict__ pbeta_p) {
    __shared__ __align__(16) float sq[16*36], sk[16*36], sv[16*36], sqz[16*36], skz[16*36];
    __shared__ float sA[16*17];
    int win = blockIdx.x, h = blockIdx.y;
    int sy = (win / NH) * 2, sx = (win % NH) * 2;
    int tid = threadIdx.x;
    float* tiles[5] = {sq, sk, sv, sqz, skz};
    const float* gsrc[5] = {g_qx, g_kx, g_vx, g_qz, g_kz};
    for (int idx = tid; idx < 640; idx += 256) {
        int t = idx >> 7, rem = idx & 127, tok = rem >> 3, f4 = rem & 7;
        int ty = tok >> 2, tx = tok & 3;
        int pix = (sy + ty)*HP + (sx + tx);
        float4 v = *(const float4*)(gsrc[t] + pix*64 + h*DHEAD + f4*4);
        *(float4*)(tiles[t] + tok*36 + f4*4) = v;
    }
    __syncthreads();
    float pb = *pbeta_p;
    float beta = fmaxf(pb, 0.f) + log1pf(__expf(-fabsf(pb))) + 1e-6f;
    int i = tid >> 4, j = tid & 15;
    float dx = 0.f, dz = 0.f;
    {
        const float4* qr  = (const float4*)(sq  + i*36);
        const float4* kr  = (const float4*)(sk  + j*36);
        const float4* qzr = (const float4*)(sqz + i*36);
        const float4* kzr = (const float4*)(skz + j*36);
        #pragma unroll
        for (int d4 = 0; d4 < 8; d4++) {
            float4 a = qr[d4],  b = kr[d4];
            float4 c = qzr[d4], e = kzr[d4];
            dx += a.x*b.x + a.y*b.y + a.z*b.z + a.w*b.w;
            dz += c.x*e.x + c.y*e.y + c.z*e.z + c.w*e.w;
        }
    }
    float s = SCALE * (dx + beta*dz);
    float mx = s;
    #pragma unroll
    for (int off = 8; off; off >>= 1) mx = fmaxf(mx, __shfl_xor_sync(0xffffffffu, mx, off, 16));
    float p = __expf(s - mx);
    float sum = p;
    #pragma unroll
    for (int off = 8; off; off >>= 1) sum += __shfl_xor_sync(0xffffffffu, sum, off, 16);
    sA[i*17 + j] = p / sum;
    __syncthreads();
    #pragma unroll
    for (int pair = 0; pair < 2; pair++) {
        int idx = tid + pair*256;
        int ii = idx >> 5, dd = idx & 31;
        float acc = 0.f;
        #pragma unroll
        for (int jj = 0; jj < 16; jj++) acc += sA[ii*17+jj] * sv[jj*36+dd];
        g_qg[h*(LTOT*DHEAD) + (win*16 + ii)*DHEAD + dd] = acc;
    }
}

// ---------------- kernel 2.5: fp32 -> fp16 (Q scaled, K, V^T), hi-only ----------------
// grid = 100 blocks x 128 threads; block handles 128 consecutive rows (head-aligned)
__global__ void prep_kernel() {
    __shared__ __align__(16) unsigned short vs[32][128];   // [d][key-local]
    const int tid = threadIdx.x;
    const int h = blockIdx.x / 50;
    const int r0 = (blockIdx.x * 128) % LTOT;
    const int g = blockIdx.x * 128 + tid;

    float qv[32];
    {
        const float4* qp = (const float4*)(g_qg + (size_t)g*DHEAD);
        #pragma unroll
        for (int i = 0; i < 8; i++) {
            float4 v = qp[i];
            qv[4*i] = v.x; qv[4*i+1] = v.y; qv[4*i+2] = v.z; qv[4*i+3] = v.w;
        }
    }
    uint32_t qu[16], ku[16];
    #pragma unroll
    for (int j = 0; j < 16; j++) {
        float a = qv[2*j], b = qv[2*j+1];
        __half ah = __float2half_rn(a), bh = __float2half_rn(b);
        uint32_t khp = ((uint32_t)__half_as_ushort(bh) << 16) | __half_as_ushort(ah);
        ku[j] = khp;
        vs[2*j][tid]   = __half_as_ushort(ah);
        vs[2*j+1][tid] = __half_as_ushort(bh);
        qu[j] = packh(a * QSCL, b * QSCL);
    }
    {
        float4* qd = (float4*)(g_qs + (size_t)g*32);
        float4* kd = (float4*)(g_ks + (size_t)g*32);
        const float4* qs4 = (const float4*)qu;
        const float4* ks4 = (const float4*)ku;
        #pragma unroll
        for (int i = 0; i < 4; i++) { qd[i] = qs4[i]; kd[i] = ks4[i]; }
    }
    __syncthreads();
    // coalesced transposed V writes: [h][d][r0 + 0..127]
    #pragma unroll
    for (int j = 0; j < 4; j++) {
        int idx = tid + j*128;            // 0..511
        int d = idx >> 4, c = idx & 15;
        float4 v = *(const float4*)&vs[d][c*8];
        *(float4*)(g_vt + ((size_t)(h*DHEAD + d))*LTOT + r0 + c*8) = v;
    }
}

// ---------------- kernel 3: persistent flash attention, single-GEMM fp16 scheme --------
// grid = 296 blocks x 256 thr (8 warps x 16 rows). Work = 5000 units of 128 keys.
// S = qh*kh; p' = 2^(s-5) via ex2.f16x2; PV = ph*vh; l = ones-column GEMM (= sum ph).
// All fp16-quantization error classes are empirically diluted ~100x (see R9/R13 ledger).
__global__ void __launch_bounds__(256, 2) flashmma_kernel() {
    extern __shared__ __align__(16) char smem[];
    const int tid = threadIdx.x, w = tid >> 5, lane = tid & 31;
    const int tg = lane >> 2, tc = lane & 3;            // groupID, threadInGroup
    const int b = blockIdx.x;
    const int ustart = (b * UTOT) / G_BLOCKS;
    const int uend = ((b + 1) * UTOT) / G_BLOCKS;
    const uint32_t sbase = smem_u32(smem);
    // per-thread ldmatrix row addresses (relative to buffer base)
    const uint32_t lmK = (uint32_t)((lane & 7)*80  + (lane >> 3)*16);
    const uint32_t lmV = (uint32_t)((lane & 7)*272 + (lane >> 3)*16);
    // constant B-fragment for the ones column (n==0): row sums land in D[:,0]
    const uint32_t ones = (tg == 0) ? 0x3C003C00u : 0u;

    // ---- cooperative tile load for global unit u (128 keys) into buffer slot ----
    auto load_unit = [&](int u, int slot) {
        const int gg = u / UPR, hh = gg / 50, kt = u % UPR;
        uint32_t db = sbase + slot*BUFB;
        const char* kg = (const char*)(g_ks + ((size_t)hh*LTOT + kt*KT)*32);
        #pragma unroll
        for (int j = 0; j < 2; j++) {
            int i = tid + j*256;                        // 0..511: 128 rows x 4 chunks
            int r = i >> 2, c = i & 3;
            cp_async16(db + B_KH + r*80 + c*16, kg + r*64 + c*16);
        }
        #pragma unroll
        for (int j = 0; j < 2; j++) {
            int i = tid + j*256;                        // 0..511: 32 d x 16 chunks
            int d = i >> 4, kgi = i & 15;
            const char* src = (const char*)(g_vt + ((size_t)(hh*DHEAD + d))*LTOT + kt*KT) + kgi*16;
            cp_async16(db + B_VTH + d*272 + kgi*16, src);
        }
        CP_COMMIT();
    };

    load_unit(ustart, 0);
    if (ustart + 1 < uend) load_unit(ustart + 1, 1);

    float oacc[4][4];
    float lacc[4];
    uint32_t qh[2][4];
    int cg = -1;

    auto flush = [&](int g) {
        const int b_first = (g*UPR*G_BLOCKS + G_BLOCKS - 1) / UTOT;
        const int slot = b - b_first;
        const int rowa = w*16 + tg, rowb = rowa + 8;
        const int pbase = (g*NSLOT + slot)*128;
        if (tc == 0) { g_pl[pbase + rowa] = lacc[0]; g_pl[pbase + rowb] = lacc[2]; }
        float2* pa  = (float2*)(g_po + ((size_t)(pbase + rowa))*DHEAD);
        float2* pbv = (float2*)(g_po + ((size_t)(pbase + rowb))*DHEAD);
        #pragma unroll
        for (int dt = 0; dt < 4; dt++) {
            pa [dt*4 + tc] = make_float2(oacc[dt][0], oacc[dt][1]);
            pbv[dt*4 + tc] = make_float2(oacc[dt][2], oacc[dt][3]);
        }
    };

    for (int u = ustart; u < uend; u++) {
        const int g = u / UPR;
        if (g != cg) {
            if (cg >= 0) flush(cg);
            cg = g;
            const int h = g / 50, qt = g % 50;
            const uint32_t* qb = (const uint32_t*)g_qs + ((size_t)h*LTOT + qt*128 + w*16)*16;
            #pragma unroll
            for (int ks = 0; ks < 2; ks++) {
                int ca = ks*8 + tc;
                qh[ks][0] = qb[tg*16     + ca];
                qh[ks][1] = qb[(tg+8)*16 + ca];
                qh[ks][2] = qb[tg*16     + ca + 4];
                qh[ks][3] = qb[(tg+8)*16 + ca + 4];
            }
            #pragma unroll
            for (int i = 0; i < 4; i++) {
                lacc[i] = 0.f;
                #pragma unroll
                for (int j = 0; j < 4; j++) oacc[i][j] = 0.f;
            }
        }

        if (u + 1 < uend) asm volatile("cp.async.wait_group 1;" ::: "memory");
        else              asm volatile("cp.async.wait_group 0;" ::: "memory");
        __syncthreads();

        const uint32_t kb = sbase + ((u - ustart) % NBUF)*BUFB;

        // ---- two 64-key halves behind one barrier ----
        #pragma unroll
        for (int s2 = 0; s2 < 2; s2++) {
            const uint32_t kK = kb + B_KH + s2*5120 + lmK;   // 64 rows x 80B per half
            const uint32_t kV = kb + B_VTH + s2*128 + lmV;   // 64-key column slice per half

            // S = Q K^T, accumulator pre-biased by SBIAS
            float sacc[8][4];
            #pragma unroll
            for (int nt = 0; nt < 8; nt++) {
                sacc[nt][0] = sacc[nt][1] = sacc[nt][2] = sacc[nt][3] = SBIAS;
                uint32_t bh[4];
                ldm_x4(bh, kK + nt*640);
                mma_f16(sacc[nt], qh[0], bh[0], bh[1]);
                mma_f16(sacc[nt], qh[1], bh[2], bh[3]);
            }

            // epilogue: p' = 2^(s-5) in f16x2; row-sum via ones-column GEMM
            uint32_t pha[4][4];
            #pragma unroll
            for (int kt2 = 0; kt2 < 4; kt2++) {
                pha[kt2][0] = ex2h2(packh(sacc[2*kt2][0],   sacc[2*kt2][1]));
                pha[kt2][1] = ex2h2(packh(sacc[2*kt2][2],   sacc[2*kt2][3]));
                pha[kt2][2] = ex2h2(packh(sacc[2*kt2+1][0], sacc[2*kt2+1][1]));
                pha[kt2][3] = ex2h2(packh(sacc[2*kt2+1][2], sacc[2*kt2+1][3]));
            }
            #pragma unroll
            for (int kt2 = 0; kt2 < 4; kt2++)
                mma_f16(lacc, pha[kt2], ones, ones);

            // O += P V
            #pragma unroll
            for (int dt = 0; dt < 4; dt++) {
                uint32_t vh[8];
                ldm_x4(vh,     kV + dt*2176);
                ldm_x4(vh + 4, kV + dt*2176 + 64);
                #pragma unroll
                for (int kt2 = 0; kt2 < 4; kt2++)
                    mma_f16(oacc[dt], pha[kt2], vh[2*kt2], vh[2*kt2+1]);
            }
        }

        // ---- prefetch unit u+2 into the buffer freed two iterations ago ----
        if (u + 2 < uend) load_unit(u + 2, (u - ustart + 2) % NBUF);
    }
    flush(cg);
}

// ---------------- kernel 4: fused slot-merge + overlap-average + proj conv + residual ----
// grid = 1600 (pixels), block = 64 (channels). Each g_po row-element is consumed
// exactly once across the grid, so inlining the merge duplicates no work.
__global__ void final_kernel(const float* __restrict__ x,
                             const float* __restrict__ Wp, const float* __restrict__ bp,
                             const float* __restrict__ pa_p, float* __restrict__ out) {
    __shared__ __align__(16) float sg[64];
    int p = blockIdx.x;
    int y = p / HW, xq = p % HW;
    int yp = y + 1, xp = xq + 1;
    int c = threadIdx.x;
    int h = c >> 5, dd = c & 31;
    int sylo = yp - 3; if (sylo < 0) sylo = 0; sylo += (sylo & 1);
    int syhi = yp > 38 ? 38 : yp;  syhi -= (syhi & 1);
    int sxlo = xp - 3; if (sxlo < 0) sxlo = 0; sxlo += (sxlo & 1);
    int sxhi = xp > 38 ? 38 : xp;  sxhi -= (sxhi & 1);
    float acc = 0.f; int cnt = 0;
    for (int sy = sylo; sy <= syhi; sy += 2)
        for (int sx = sxlo; sx <= sxhi; sx += 2) {
            int ty = yp - sy, tx = xp - sx;
            int lw = ((sy >> 1)*NH + (sx >> 1))*NTOK + ty*4 + tx;
            int qt = lw >> 7, rowlocal = lw & 127;
            int g = h*50 + qt;
            int b_first = (g*UPR*G_BLOCKS + G_BLOCKS - 1) / UTOT;
            int b_last  = ((g+1)*UPR*G_BLOCKS - 1) / UTOT;
            int ns = b_last - b_first + 1;
            float l = 0.f, v = 0.f;
            for (int s = 0; s < ns; s++) {
                int pb_ = (g*NSLOT + s)*128 + rowlocal;
                l += g_pl[pb_];
                v += g_po[(size_t)pb_*DHEAD + dd];
            }
            acc += __fdividef(v, l);
            cnt++;
        }
    sg[c] = acc / ((float)cnt + 1e-6f);
    __syncthreads();
    float a = 2.f / (1.f + __expf(-(*pa_p)));
    float pr = bp[c];
    const float4* wrow = (const float4*)(Wp + c*64);
    #pragma unroll
    for (int i = 0; i < 16; i++) {
        float4 w = wrow[i];
        float4 g = *(const float4*)(sg + i*4);
        pr += w.x*g.x + w.y*g.y + w.z*g.z + w.w*g.w;
    }
    int oi = c*1600 + y*HW + xq;
    out[oi] = x[oi] + a*pr;
}

// ---------------- launcher ----------------
extern "C" void kernel_launch(void* const* d_in, const int* in_sizes, int n_in,
                              void* d_out, int out_size) {
    (void)in_sizes; (void)n_in; (void)out_size;
    const float* x     = (const float*)d_in[0];
    const float* z     = (const float*)d_in[1];
    const float* Wqkv  = (const float*)d_in[2];
    const float* bqkv  = (const float*)d_in[3];
    const float* Wqkz  = (const float*)d_in[4];
    const float* bqkz  = (const float*)d_in[5];
    const float* Wproj = (const float*)d_in[6];
    const float* bproj = (const float*)d_in[7];
    const float* pa    = (const float*)d_in[8];
    const float* pbeta = (const float*)d_in[9];
    float* out = (float*)d_out;

    cudaFuncSetAttribute(flashmma_kernel, cudaFuncAttributeMaxDynamicSharedMemorySize, SMEM_FL);

    proj_kernel<<<dim3(HP, 4), 320>>>(x, z, Wqkv, bqkv, Wqkz, bqkz);
    local_attn_kernel<<<dim3(NWIN, HEADS), 256>>>(pbeta);
    prep_kernel<<<100, 128>>>();
    flashmma_kernel<<<G_BLOCKS, 256, SMEM_FL>>>();
    final_kernel<<<HW*HW, 64>>>(x, Wproj, bproj, pa, out);
}

// round 16
// speedup vs baseline: 1.3814x; 1.0220x over previous
#include <cuda_runtime.h>
#include <cuda_fp16.h>
#include <cstdint>
#include <math.h>

// ---------------- problem constants ----------------
#define HEADS 2
#define DHEAD 32
#define HW    40
#define HP    42
#define NPIX  (HP*HP)
#define NH    20
#define NWIN  400
#define NTOK  16
#define LTOT  6400
#define SCALE 0.17677669529663687f
#define QSCL  (0.17677669529663687f * 1.4426950408889634f)  // SCALE * log2(e)
#define SBIAS (-5.0f)   // exponent bias: p' = 2^(s-5), cancels in o = sum(p'v)/sum(p')

// flash work decomposition (persistent balanced schedule)
#define KT        128         // keys per unit (two 64-key halves per sync)
#define UPR       50          // units per row-group (6400/128)
#define NRG       100         // row-groups: 2 heads x 50 q-tiles of 128 rows
#define UTOT      (NRG*UPR)   // 5000
#define G_BLOCKS  296         // exactly 2 blocks/SM x 148 SMs -> uniform 16 warps/SM
#define NSLOT     4           // max blocks intersecting one row-group
// smem byte offsets within one buffer (unit = 128 keys, hi-splits only)
#define B_KH   0              // 128 keys x 80B (64B fp16 data + 16 pad)
#define B_VTH  10240          // 32 dims x 272B (256B fp16 data + 16 pad)
#define BUFB   18944
#define NBUF   3
#define SMEM_FL (NBUF*BUFB)   // 56832 bytes dynamic

// ---------------- scratch ----------------
__device__ float g_qx[NPIX*64];
__device__ float g_kx[NPIX*64];
__device__ float g_vx[NPIX*64];
__device__ float g_qz[NPIX*64];
__device__ float g_kz[NPIX*64];
__device__ __align__(256) unsigned short g_qs[HEADS*LTOT*32];   // fp16(q*QSCL)
__device__ __align__(256) unsigned short g_ks[HEADS*LTOT*32];   // fp16(k)
__device__ __align__(256) unsigned short g_vt[HEADS*DHEAD*LTOT];// [h][d][key] fp16(v)
__device__ float g_po[NRG*NSLOT*128*DHEAD];         // partial unnormalized O per (rg, slot)
__device__ float g_pl[NRG*NSLOT*128];               // partial expsum per (rg, slot)

// ---------------- helpers ----------------
static __device__ __forceinline__ uint32_t smem_u32(const void* p) {
    uint32_t a;
    asm("{ .reg .u64 t; cvta.to.shared.u64 t, %1; cvt.u32.u64 %0, t; }" : "=r"(a) : "l"(p));
    return a;
}
static __device__ __forceinline__ uint32_t packh(float lo, float hi) {
    uint32_t r; asm("cvt.rn.satfinite.f16x2.f32 %0, %1, %2;" : "=r"(r) : "f"(hi), "f"(lo)); return r;
}
static __device__ __forceinline__ uint32_t ex2h2(uint32_t a) {
    uint32_t r; asm("ex2.approx.f16x2 %0, %1;" : "=r"(r) : "r"(a)); return r;
}
// mma.sync m16n8k16 fp16 with fp32 accum (sm_80+ baseline PTX; Blackwell tensor pipe)
static __device__ __forceinline__ void mma_f16(float* d, const uint32_t* a, uint32_t b0, uint32_t b1) {
    asm volatile("mma.sync.aligned.m16n8k16.row.col.f32.f16.f16.f32 "
        "{%0,%1,%2,%3}, {%4,%5,%6,%7}, {%8,%9}, {%0,%1,%2,%3};"
        : "+f"(d[0]), "+f"(d[1]), "+f"(d[2]), "+f"(d[3])
        : "r"(a[0]), "r"(a[1]), "r"(a[2]), "r"(a[3]), "r"(b0), "r"(b1));
}
// ldmatrix x4: one issue slot loads four 8x8 b16 fragments
static __device__ __forceinline__ void ldm_x4(uint32_t* r, uint32_t addr) {
    asm volatile("ldmatrix.sync.aligned.m8n8.x4.shared.b16 {%0,%1,%2,%3}, [%4];"
        : "=r"(r[0]), "=r"(r[1]), "=r"(r[2]), "=r"(r[3]) : "r"(addr));
}
static __device__ __forceinline__ void cp_async16(uint32_t dst, const void* src) {
    asm volatile("cp.async.cg.shared.global [%0], [%1], 16;" :: "r"(dst), "l"(src));
}
#define CP_COMMIT() asm volatile("cp.async.commit_group;" ::: "memory")

static __device__ __forceinline__ int reflect40(int v) {
    return v < 0 ? -v : (v > 39 ? 78 - v : v);
}

// ---------------- kernel 1: conv1x1 projections with reflect pad ----------------
// grid = (42, 4): row yp, pixel chunk of <=11. block = 320 (one thread per out channel)
__global__ void proj_kernel(const float* __restrict__ x, const float* __restrict__ z,
                            const float* __restrict__ Wx, const float* __restrict__ bx,
                            const float* __restrict__ Wz, const float* __restrict__ bz) {
    __shared__ __align__(16) float xs[11*68];
    __shared__ __align__(16) float zs[11*68];
    int yp = blockIdx.x;
    int x0 = blockIdx.y * 11;
    int x1 = x0 + 11; if (x1 > HP) x1 = HP;
    int npx = x1 - x0;
    int ys = reflect40(yp - 1);
    for (int idx = threadIdx.x; idx < 11*64; idx += blockDim.x) {
        int c = idx / 11, lx = idx % 11;
        if (lx < npx) {
            int xsrc = reflect40(x0 + lx - 1);
            int src = c*1600 + ys*HW + xsrc;
            xs[lx*68 + c] = x[src];
            zs[lx*68 + c] = z[src];
        }
    }
    __syncthreads();
    int oc = threadIdx.x;
    const float* wrow; float bias; float* dst; int cout; const float* sm;
    if (oc < 192) {
        wrow = Wx + oc*64; bias = bx[oc];
        int t = oc >> 6; cout = oc & 63;
        dst = (t == 0) ? g_qx : (t == 1 ? g_kx : g_vx);
        sm = xs;
    } else {
        int ozc = oc - 192;
        wrow = Wz + ozc*64; bias = bz[ozc];
        cout = ozc & 63;
        dst = (ozc < 64) ? g_qz : g_kz;
        sm = zs;
    }
    float4 wr[16];
    #pragma unroll
    for (int i = 0; i < 16; i++) wr[i] = ((const float4*)wrow)[i];
    for (int lx = 0; lx < npx; lx++) {
        float acc = bias;
        #pragma unroll
        for (int i = 0; i < 16; i++) {
            float4 v = *(const float4*)(sm + lx*68 + i*4);
            acc += wr[i].x*v.x + wr[i].y*v.y + wr[i].z*v.z + wr[i].w*v.w;
        }
        dst[(yp*HP + x0 + lx)*64 + cout] = acc;
    }
}

// ---------------- kernel 2: local window attention + fused fp16 emission ----------------
// grid = (400, 2) = (window, head), block = 256. Emits g_qs/g_ks/g_vt directly
// (local output == flash Q=K=V; V^T goes through a padded smem transpose for
// 32B-contiguous global stores).
__global__ void local_attn_kernel(const float* __restrict__ pbeta_p) {
    __shared__ __align__(16) float sq[16*36], sk[16*36], sv[16*36], sqz[16*36], skz[16*36];
    __shared__ float sA[16*17];
    __shared__ __align__(16) unsigned short vh16[32][18];   // [dim][key-local], pad 18 (9 words, coprime 32)
    int win = blockIdx.x, h = blockIdx.y;
    int sy = (win / NH) * 2, sx = (win % NH) * 2;
    int tid = threadIdx.x;
    float* tiles[5] = {sq, sk, sv, sqz, skz};
    const float* gsrc[5] = {g_qx, g_kx, g_vx, g_qz, g_kz};
    for (int idx = tid; idx < 640; idx += 256) {
        int t = idx >> 7, rem = idx & 127, tok = rem >> 3, f4 = rem & 7;
        int ty = tok >> 2, tx = tok & 3;
        int pix = (sy + ty)*HP + (sx + tx);
        float4 v = *(const float4*)(gsrc[t] + pix*64 + h*DHEAD + f4*4);
        *(float4*)(tiles[t] + tok*36 + f4*4) = v;
    }
    __syncthreads();
    float pb = *pbeta_p;
    float beta = fmaxf(pb, 0.f) + log1pf(__expf(-fabsf(pb))) + 1e-6f;
    int i = tid >> 4, j = tid & 15;
    float dx = 0.f, dz = 0.f;
    {
        const float4* qr  = (const float4*)(sq  + i*36);
        const float4* kr  = (const float4*)(sk  + j*36);
        const float4* qzr = (const float4*)(sqz + i*36);
        const float4* kzr = (const float4*)(skz + j*36);
        #pragma unroll
        for (int d4 = 0; d4 < 8; d4++) {
            float4 a = qr[d4],  b = kr[d4];
            float4 c = qzr[d4], e = kzr[d4];
            dx += a.x*b.x + a.y*b.y + a.z*b.z + a.w*b.w;
            dz += c.x*e.x + c.y*e.y + c.z*e.z + c.w*e.w;
        }
    }
    float s = SCALE * (dx + beta*dz);
    float mx = s;
    #pragma unroll
    for (int off = 8; off; off >>= 1) mx = fmaxf(mx, __shfl_xor_sync(0xffffffffu, mx, off, 16));
    float p = __expf(s - mx);
    float sum = p;
    #pragma unroll
    for (int off = 8; off; off >>= 1) sum += __shfl_xor_sync(0xffffffffu, sum, off, 16);
    sA[i*17 + j] = p / sum;
    __syncthreads();
    #pragma unroll
    for (int pair = 0; pair < 2; pair++) {
        int idx = tid + pair*256;
        int ii = idx >> 5, dd = idx & 31;
        float acc = 0.f;
        #pragma unroll
        for (int jj = 0; jj < 16; jj++) acc += sA[ii*17+jj] * sv[jj*36+dd];
        // fp16 emission: q (scaled) and k (== v) hi parts
        __half ah = __float2half_rn(acc);
        unsigned short uh = __half_as_ushort(ah);
        size_t rb = (size_t)h*LTOT + win*16 + ii;
        g_qs[rb*32 + dd] = __half_as_ushort(__float2half_rn(acc * QSCL));
        g_ks[rb*32 + dd] = uh;
        vh16[dd][ii] = uh;
    }
    __syncthreads();
    // transposed V store: 8 threads per dim cover 16 keys (32B contiguous)
    {
        int d = tid >> 3, kp = (tid & 7)*2;
        uint32_t val = *(const uint32_t*)&vh16[d][kp];
        *(uint32_t*)(g_vt + ((size_t)(h*DHEAD + d))*LTOT + win*16 + kp) = val;
    }
}

// ---------------- kernel 3: persistent flash attention, single-GEMM fp16 scheme --------
// grid = 296 blocks x 256 thr (8 warps x 16 rows). Work = 5000 units of 128 keys.
// S = qh*kh; p' = 2^(s-5) via ex2.f16x2; PV = ph*vh; l = ones-column GEMM (= sum ph).
__global__ void __launch_bounds__(256, 2) flashmma_kernel() {
    extern __shared__ __align__(16) char smem[];
    const int tid = threadIdx.x, w = tid >> 5, lane = tid & 31;
    const int tg = lane >> 2, tc = lane & 3;            // groupID, threadInGroup
    const int b = blockIdx.x;
    const int ustart = (b * UTOT) / G_BLOCKS;
    const int uend = ((b + 1) * UTOT) / G_BLOCKS;
    const uint32_t sbase = smem_u32(smem);
    // per-thread ldmatrix row addresses (relative to buffer base)
    const uint32_t lmK = (uint32_t)((lane & 7)*80  + (lane >> 3)*16);
    const uint32_t lmV = (uint32_t)((lane & 7)*272 + (lane >> 3)*16);
    // constant B-fragment for the ones column (n==0): row sums land in D[:,0]
    const uint32_t ones = (tg == 0) ? 0x3C003C00u : 0u;

    // ---- cooperative tile load for global unit u (128 keys) into buffer slot ----
    auto load_unit = [&](int u, int slot) {
        const int gg = u / UPR, hh = gg / 50, kt = u % UPR;
        uint32_t db = sbase + slot*BUFB;
        const char* kg = (const char*)(g_ks + ((size_t)hh*LTOT + kt*KT)*32);
        #pragma unroll
        for (int j = 0; j < 2; j++) {
            int i = tid + j*256;                        // 0..511: 128 rows x 4 chunks
            int r = i >> 2, c = i & 3;
            cp_async16(db + B_KH + r*80 + c*16, kg + r*64 + c*16);
        }
        #pragma unroll
        for (int j = 0; j < 2; j++) {
            int i = tid + j*256;                        // 0..511: 32 d x 16 chunks
            int d = i >> 4, kgi = i & 15;
            const char* src = (const char*)(g_vt + ((size_t)(hh*DHEAD + d))*LTOT + kt*KT) + kgi*16;
            cp_async16(db + B_VTH + d*272 + kgi*16, src);
        }
        CP_COMMIT();
    };

    load_unit(ustart, 0);
    if (ustart + 1 < uend) load_unit(ustart + 1, 1);

    float oacc[4][4];
    float lacc[4];
    uint32_t qh[2][4];
    int cg = -1;

    auto flush = [&](int g) {
        const int b_first = (g*UPR*G_BLOCKS + G_BLOCKS - 1) / UTOT;
        const int slot = b - b_first;
        const int rowa = w*16 + tg, rowb = rowa + 8;
        const int pbase = (g*NSLOT + slot)*128;
        if (tc == 0) { g_pl[pbase + rowa] = lacc[0]; g_pl[pbase + rowb] = lacc[2]; }
        float2* pa  = (float2*)(g_po + ((size_t)(pbase + rowa))*DHEAD);
        float2* pbv = (float2*)(g_po + ((size_t)(pbase + rowb))*DHEAD);
        #pragma unroll
        for (int dt = 0; dt < 4; dt++) {
            pa [dt*4 + tc] = make_float2(oacc[dt][0], oacc[dt][1]);
            pbv[dt*4 + tc] = make_float2(oacc[dt][2], oacc[dt][3]);
        }
    };

    for (int u = ustart; u < uend; u++) {
        const int g = u / UPR;
        if (g != cg) {
            if (cg >= 0) flush(cg);
            cg = g;
            const int h = g / 50, qt = g % 50;
            const uint32_t* qb = (const uint32_t*)g_qs + ((size_t)h*LTOT + qt*128 + w*16)*16;
            #pragma unroll
            for (int ks = 0; ks < 2; ks++) {
                int ca = ks*8 + tc;
                qh[ks][0] = qb[tg*16     + ca];
                qh[ks][1] = qb[(tg+8)*16 + ca];
                qh[ks][2] = qb[tg*16     + ca + 4];
                qh[ks][3] = qb[(tg+8)*16 + ca + 4];
            }
            #pragma unroll
            for (int i = 0; i < 4; i++) {
                lacc[i] = 0.f;
                #pragma unroll
                for (int j = 0; j < 4; j++) oacc[i][j] = 0.f;
            }
        }

        if (u + 1 < uend) asm volatile("cp.async.wait_group 1;" ::: "memory");
        else              asm volatile("cp.async.wait_group 0;" ::: "memory");
        __syncthreads();

        const uint32_t kb = sbase + ((u - ustart) % NBUF)*BUFB;

        // ---- two 64-key halves behind one barrier ----
        #pragma unroll
        for (int s2 = 0; s2 < 2; s2++) {
            const uint32_t kK = kb + B_KH + s2*5120 + lmK;   // 64 rows x 80B per half
            const uint32_t kV = kb + B_VTH + s2*128 + lmV;   // 64-key column slice per half

            // S = Q K^T, accumulator pre-biased by SBIAS
            float sacc[8][4];
            #pragma unroll
            for (int nt = 0; nt < 8; nt++) {
                sacc[nt][0] = sacc[nt][1] = sacc[nt][2] = sacc[nt][3] = SBIAS;
                uint32_t bh[4];
                ldm_x4(bh, kK + nt*640);
                mma_f16(sacc[nt], qh[0], bh[0], bh[1]);
                mma_f16(sacc[nt], qh[1], bh[2], bh[3]);
            }

            // epilogue: p' = 2^(s-5) in f16x2; row-sum via ones-column GEMM
            uint32_t pha[4][4];
            #pragma unroll
            for (int kt2 = 0; kt2 < 4; kt2++) {
                pha[kt2][0] = ex2h2(packh(sacc[2*kt2][0],   sacc[2*kt2][1]));
                pha[kt2][1] = ex2h2(packh(sacc[2*kt2][2],   sacc[2*kt2][3]));
                pha[kt2][2] = ex2h2(packh(sacc[2*kt2+1][0], sacc[2*kt2+1][1]));
                pha[kt2][3] = ex2h2(packh(sacc[2*kt2+1][2], sacc[2*kt2+1][3]));
            }
            #pragma unroll
            for (int kt2 = 0; kt2 < 4; kt2++)
                mma_f16(lacc, pha[kt2], ones, ones);

            // O += P V
            #pragma unroll
            for (int dt = 0; dt < 4; dt++) {
                uint32_t vh[8];
                ldm_x4(vh,     kV + dt*2176);
                ldm_x4(vh + 4, kV + dt*2176 + 64);
                #pragma unroll
                for (int kt2 = 0; kt2 < 4; kt2++)
                    mma_f16(oacc[dt], pha[kt2], vh[2*kt2], vh[2*kt2+1]);
            }
        }

        // ---- prefetch unit u+2 into the buffer freed two iterations ago ----
        if (u + 2 < uend) load_unit(u + 2, (u - ustart + 2) % NBUF);
    }
    flush(cg);
}

// ---------------- kernel 4: fused slot-merge + overlap-average + proj conv + residual ----
// grid = 400 blocks x 256 thr: 4 pixels per block (64 channels each) for Wp reuse.
__global__ void final_kernel(const float* __restrict__ x,
                             const float* __restrict__ Wp, const float* __restrict__ bp,
                             const float* __restrict__ pa_p, float* __restrict__ out) {
    __shared__ __align__(16) float sg[4][68];
    int pl = threadIdx.x >> 6, c = threadIdx.x & 63;
    int p = blockIdx.x*4 + pl;
    int y = p / HW, xq = p % HW;
    int yp = y + 1, xp = xq + 1;
    int h = c >> 5, dd = c & 31;
    int sylo = yp - 3; if (sylo < 0) sylo = 0; sylo += (sylo & 1);
    int syhi = yp > 38 ? 38 : yp;  syhi -= (syhi & 1);
    int sxlo = xp - 3; if (sxlo < 0) sxlo = 0; sxlo += (sxlo & 1);
    int sxhi = xp > 38 ? 38 : xp;  sxhi -= (sxhi & 1);
    float acc = 0.f; int cnt = 0;
    for (int sy = sylo; sy <= syhi; sy += 2)
        for (int sx = sxlo; sx <= sxhi; sx += 2) {
            int ty = yp - sy, tx = xp - sx;
            int lw = ((sy >> 1)*NH + (sx >> 1))*NTOK + ty*4 + tx;
            int qt = lw >> 7, rowlocal = lw & 127;
            int g = h*50 + qt;
            int b_first = (g*UPR*G_BLOCKS + G_BLOCKS - 1) / UTOT;
            int b_last  = ((g+1)*UPR*G_BLOCKS - 1) / UTOT;
            int ns = b_last - b_first + 1;
            float l = 0.f, v = 0.f;
            for (int s = 0; s < ns; s++) {
                int pb_ = (g*NSLOT + s)*128 + rowlocal;
                l += g_pl[pb_];
                v += g_po[(size_t)pb_*DHEAD + dd];
            }
            acc += __fdividef(v, l);
            cnt++;
        }
    sg[pl][c] = acc / ((float)cnt + 1e-6f);
    __syncthreads();
    float a = 2.f / (1.f + __expf(-(*pa_p)));
    float pr = bp[c];
    const float4* wrow = (const float4*)(Wp + c*64);
    #pragma unroll
    for (int i = 0; i < 16; i++) {
        float4 w = wrow[i];
        float4 g = *(const float4*)(&sg[pl][i*4]);
        pr += w.x*g.x + w.y*g.y + w.z*g.z + w.w*g.w;
    }
    int oi = c*1600 + y*HW + xq;
    out[oi] = x[oi] + a*pr;
}

// ---------------- launcher ----------------
extern "C" void kernel_launch(void* const* d_in, const int* in_sizes, int n_in,
                              void* d_out, int out_size) {
    (void)in_sizes; (void)n_in; (void)out_size;
    const float* x     = (const float*)d_in[0];
    const float* z     = (const float*)d_in[1];
    const float* Wqkv  = (const float*)d_in[2];
    const float* bqkv  = (const float*)d_in[3];
    const float* Wqkz  = (const float*)d_in[4];
    const float* bqkz  = (const float*)d_in[5];
    const float* Wproj = (const float*)d_in[6];
    const float* bproj = (const float*)d_in[7];
    const float* pa    = (const float*)d_in[8];
    const float* pbeta = (const float*)d_in[9];
    float* out = (float*)d_out;

    cudaFuncSetAttribute(flashmma_kernel, cudaFuncAttributeMaxDynamicSharedMemorySize, SMEM_FL);

    proj_kernel<<<dim3(HP, 4), 320>>>(x, z, Wqkv, bqkv, Wqkz, bqkz);
    local_attn_kernel<<<dim3(NWIN, HEADS), 256>>>(pbeta);
    flashmma_kernel<<<G_BLOCKS, 256, SMEM_FL>>>();
    final_kernel<<<HW*HW/4, 256>>>(x, Wproj, bproj, pa, out);
}

// round 17
// speedup vs baseline: 1.3898x; 1.0061x over previous
#include <cuda_runtime.h>
#include <cuda_fp16.h>
#include <cstdint>
#include <math.h>

// ---------------- problem constants ----------------
#define HEADS 2
#define DHEAD 32
#define HW    40
#define HP    42
#define NPIX  (HP*HP)
#define NH    20
#define NWIN  400
#define NTOK  16
#define LTOT  6400
#define SCALE 0.17677669529663687f
#define QSCL  (0.17677669529663687f * 1.4426950408889634f)  // SCALE * log2(e)
#define SBIAS (-5.0f)   // exponent bias: p' = 2^(s-5), cancels in o = sum(p'v)/sum(p')

// flash work decomposition (persistent balanced schedule)
#define KT        128         // keys per unit (two 64-key halves per sync)
#define UPR       50          // units per row-group (6400/128)
#define NRG       100         // row-groups: 2 heads x 50 q-tiles of 128 rows
#define UTOT      (NRG*UPR)   // 5000
#define G_BLOCKS  296         // exactly 2 blocks/SM x 148 SMs -> uniform 16 warps/SM
#define NSLOT     4           // max blocks intersecting one row-group
// smem byte offsets within one buffer (unit = 128 keys, hi-splits only)
#define B_KH   0              // 128 keys x 80B (64B fp16 data + 16 pad)
#define B_VTH  10240          // 32 dims x 272B (256B fp16 data + 16 pad)
#define BUFB   18944
#define NBUF   3
#define SMEM_FL (NBUF*BUFB)   // 56832 bytes dynamic

// ---------------- scratch ----------------
__device__ float g_qx[NPIX*64];
__device__ float g_kx[NPIX*64];
__device__ float g_vx[NPIX*64];
__device__ float g_qz[NPIX*64];
__device__ float g_kz[NPIX*64];
__device__ __align__(256) unsigned short g_qs[HEADS*LTOT*32];   // fp16(q*QSCL)
__device__ __align__(256) unsigned short g_ks[HEADS*LTOT*32];   // fp16(k)
__device__ __align__(256) unsigned short g_vt[HEADS*DHEAD*LTOT];// [h][d][key] fp16(v)
// zero-initialized; flashmma writes only live slots, unwritten slots stay 0 forever
__device__ float g_po[NRG*NSLOT*128*DHEAD];         // partial unnormalized O per (rg, slot)
__device__ float g_pl[NRG*NSLOT*128];               // partial expsum per (rg, slot)

// ---------------- helpers ----------------
static __device__ __forceinline__ uint32_t smem_u32(const void* p) {
    uint32_t a;
    asm("{ .reg .u64 t; cvta.to.shared.u64 t, %1; cvt.u32.u64 %0, t; }" : "=r"(a) : "l"(p));
    return a;
}
static __device__ __forceinline__ uint32_t packh(float lo, float hi) {
    uint32_t r; asm("cvt.rn.satfinite.f16x2.f32 %0, %1, %2;" : "=r"(r) : "f"(hi), "f"(lo)); return r;
}
static __device__ __forceinline__ uint32_t ex2h2(uint32_t a) {
    uint32_t r; asm("ex2.approx.f16x2 %0, %1;" : "=r"(r) : "r"(a)); return r;
}
// mma.sync m16n8k16 fp16 with fp32 accum (sm_80+ baseline PTX; Blackwell tensor pipe)
static __device__ __forceinline__ void mma_f16(float* d, const uint32_t* a, uint32_t b0, uint32_t b1) {
    asm volatile("mma.sync.aligned.m16n8k16.row.col.f32.f16.f16.f32 "
        "{%0,%1,%2,%3}, {%4,%5,%6,%7}, {%8,%9}, {%0,%1,%2,%3};"
        : "+f"(d[0]), "+f"(d[1]), "+f"(d[2]), "+f"(d[3])
        : "r"(a[0]), "r"(a[1]), "r"(a[2]), "r"(a[3]), "r"(b0), "r"(b1));
}
// ldmatrix x4: one issue slot loads four 8x8 b16 fragments
static __device__ __forceinline__ void ldm_x4(uint32_t* r, uint32_t addr) {
    asm volatile("ldmatrix.sync.aligned.m8n8.x4.shared.b16 {%0,%1,%2,%3}, [%4];"
        : "=r"(r[0]), "=r"(r[1]), "=r"(r[2]), "=r"(r[3]) : "r"(addr));
}
static __device__ __forceinline__ void cp_async16(uint32_t dst, const void* src) {
    asm volatile("cp.async.cg.shared.global [%0], [%1], 16;" :: "r"(dst), "l"(src));
}
#define CP_COMMIT() asm volatile("cp.async.commit_group;" ::: "memory")

static __device__ __forceinline__ int reflect40(int v) {
    return v < 0 ? -v : (v > 39 ? 78 - v : v);
}

// ---------------- kernel 1: conv1x1 projections with reflect pad ----------------
// grid = (42, 4): row yp, pixel chunk of <=11. block = 320 (one thread per out channel)
__global__ void proj_kernel(const float* __restrict__ x, const float* __restrict__ z,
                            const float* __restrict__ Wx, const float* __restrict__ bx,
                            const float* __restrict__ Wz, const float* __restrict__ bz) {
    __shared__ __align__(16) float xs[11*68];
    __shared__ __align__(16) float zs[11*68];
    int yp = blockIdx.x;
    int x0 = blockIdx.y * 11;
    int x1 = x0 + 11; if (x1 > HP) x1 = HP;
    int npx = x1 - x0;
    int ys = reflect40(yp - 1);
    for (int idx = threadIdx.x; idx < 11*64; idx += blockDim.x) {
        int c = idx / 11, lx = idx % 11;
        if (lx < npx) {
            int xsrc = reflect40(x0 + lx - 1);
            int src = c*1600 + ys*HW + xsrc;
            xs[lx*68 + c] = x[src];
            zs[lx*68 + c] = z[src];
        }
    }
    __syncthreads();
    int oc = threadIdx.x;
    const float* wrow; float bias; float* dst; int cout; const float* sm;
    if (oc < 192) {
        wrow = Wx + oc*64; bias = bx[oc];
        int t = oc >> 6; cout = oc & 63;
        dst = (t == 0) ? g_qx : (t == 1 ? g_kx : g_vx);
        sm = xs;
    } else {
        int ozc = oc - 192;
        wrow = Wz + ozc*64; bias = bz[ozc];
        cout = ozc & 63;
        dst = (ozc < 64) ? g_qz : g_kz;
        sm = zs;
    }
    float4 wr[16];
    #pragma unroll
    for (int i = 0; i < 16; i++) wr[i] = ((const float4*)wrow)[i];
    for (int lx = 0; lx < npx; lx++) {
        float acc = bias;
        #pragma unroll
        for (int i = 0; i < 16; i++) {
            float4 v = *(const float4*)(sm + lx*68 + i*4);
            acc += wr[i].x*v.x + wr[i].y*v.y + wr[i].z*v.z + wr[i].w*v.w;
        }
        dst[(yp*HP + x0 + lx)*64 + cout] = acc;
    }
}

// ---------------- kernel 2: local window attention + fused fp16 emission ----------------
// grid = (400, 2) = (window, head), block = 256. Emits g_qs/g_ks/g_vt directly
// (local output == flash Q=K=V; V^T goes through a padded smem transpose for
// 32B-contiguous global stores).
__global__ void local_attn_kernel(const float* __restrict__ pbeta_p) {
    __shared__ __align__(16) float sq[16*36], sk[16*36], sv[16*36], sqz[16*36], skz[16*36];
    __shared__ float sA[16*17];
    __shared__ __align__(16) unsigned short vh16[32][18];   // [dim][key-local], pad 18 (9 words, coprime 32)
    int win = blockIdx.x, h = blockIdx.y;
    int sy = (win / NH) * 2, sx = (win % NH) * 2;
    int tid = threadIdx.x;
    float* tiles[5] = {sq, sk, sv, sqz, skz};
    const float* gsrc[5] = {g_qx, g_kx, g_vx, g_qz, g_kz};
    for (int idx = tid; idx < 640; idx += 256) {
        int t = idx >> 7, rem = idx & 127, tok = rem >> 3, f4 = rem & 7;
        int ty = tok >> 2, tx = tok & 3;
        int pix = (sy + ty)*HP + (sx + tx);
        float4 v = *(const float4*)(gsrc[t] + pix*64 + h*DHEAD + f4*4);
        *(float4*)(tiles[t] + tok*36 + f4*4) = v;
    }
    __syncthreads();
    float pb = *pbeta_p;
    float beta = fmaxf(pb, 0.f) + log1pf(__expf(-fabsf(pb))) + 1e-6f;
    int i = tid >> 4, j = tid & 15;
    float dx = 0.f, dz = 0.f;
    {
        const float4* qr  = (const float4*)(sq  + i*36);
        const float4* kr  = (const float4*)(sk  + j*36);
        const float4* qzr = (const float4*)(sqz + i*36);
        const float4* kzr = (const float4*)(skz + j*36);
        #pragma unroll
        for (int d4 = 0; d4 < 8; d4++) {
            float4 a = qr[d4],  b = kr[d4];
            float4 c = qzr[d4], e = kzr[d4];
            dx += a.x*b.x + a.y*b.y + a.z*b.z + a.w*b.w;
            dz += c.x*e.x + c.y*e.y + c.z*e.z + c.w*e.w;
        }
    }
    float s = SCALE * (dx + beta*dz);
    float mx = s;
    #pragma unroll
    for (int off = 8; off; off >>= 1) mx = fmaxf(mx, __shfl_xor_sync(0xffffffffu, mx, off, 16));
    float p = __expf(s - mx);
    float sum = p;
    #pragma unroll
    for (int off = 8; off; off >>= 1) sum += __shfl_xor_sync(0xffffffffu, sum, off, 16);
    sA[i*17 + j] = p / sum;
    __syncthreads();
    #pragma unroll
    for (int pair = 0; pair < 2; pair++) {
        int idx = tid + pair*256;
        int ii = idx >> 5, dd = idx & 31;
        float acc = 0.f;
        #pragma unroll
        for (int jj = 0; jj < 16; jj++) acc += sA[ii*17+jj] * sv[jj*36+dd];
        // fp16 emission: q (scaled) and k (== v) hi parts
        __half ah = __float2half_rn(acc);
        unsigned short uh = __half_as_ushort(ah);
        size_t rb = (size_t)h*LTOT + win*16 + ii;
        g_qs[rb*32 + dd] = __half_as_ushort(__float2half_rn(acc * QSCL));
        g_ks[rb*32 + dd] = uh;
        vh16[dd][ii] = uh;
    }
    __syncthreads();
    // transposed V store: 8 threads per dim cover 16 keys (32B contiguous)
    {
        int d = tid >> 3, kp = (tid & 7)*2;
        uint32_t val = *(const uint32_t*)&vh16[d][kp];
        *(uint32_t*)(g_vt + ((size_t)(h*DHEAD + d))*LTOT + win*16 + kp) = val;
    }
}

// ---------------- kernel 3: persistent flash attention, single-GEMM fp16 scheme --------
// grid = 296 blocks x 256 thr (8 warps x 16 rows). Work = 5000 units of 128 keys.
// S = qh*kh; p' = 2^(s-5) via ex2.f16x2; PV = ph*vh; l = ones-column GEMM (= sum ph).
__global__ void __launch_bounds__(256, 2) flashmma_kernel() {
    extern __shared__ __align__(16) char smem[];
    const int tid = threadIdx.x, w = tid >> 5, lane = tid & 31;
    const int tg = lane >> 2, tc = lane & 3;            // groupID, threadInGroup
    const int b = blockIdx.x;
    const int ustart = (b * UTOT) / G_BLOCKS;
    const int uend = ((b + 1) * UTOT) / G_BLOCKS;
    const uint32_t sbase = smem_u32(smem);
    // per-thread ldmatrix row addresses (relative to buffer base)
    const uint32_t lmK = (uint32_t)((lane & 7)*80  + (lane >> 3)*16);
    const uint32_t lmV = (uint32_t)((lane & 7)*272 + (lane >> 3)*16);
    // constant B-fragment for the ones column (n==0): row sums land in D[:,0]
    const uint32_t ones = (tg == 0) ? 0x3C003C00u : 0u;

    // ---- cooperative tile load for global unit u (128 keys) into buffer slot ----
    auto load_unit = [&](int u, int slot) {
        const int gg = u / UPR, hh = gg / 50, kt = u % UPR;
        uint32_t db = sbase + slot*BUFB;
        const char* kg = (const char*)(g_ks + ((size_t)hh*LTOT + kt*KT)*32);
        #pragma unroll
        for (int j = 0; j < 2; j++) {
            int i = tid + j*256;                        // 0..511: 128 rows x 4 chunks
            int r = i >> 2, c = i & 3;
            cp_async16(db + B_KH + r*80 + c*16, kg + r*64 + c*16);
        }
        #pragma unroll
        for (int j = 0; j < 2; j++) {
            int i = tid + j*256;                        // 0..511: 32 d x 16 chunks
            int d = i >> 4, kgi = i & 15;
            const char* src = (const char*)(g_vt + ((size_t)(hh*DHEAD + d))*LTOT + kt*KT) + kgi*16;
            cp_async16(db + B_VTH + d*272 + kgi*16, src);
        }
        CP_COMMIT();
    };

    load_unit(ustart, 0);
    if (ustart + 1 < uend) load_unit(ustart + 1, 1);

    float oacc[4][4];
    float lacc[4];
    uint32_t qh[2][4];
    int cg = -1;

    auto flush = [&](int g) {
        const int b_first = (g*UPR*G_BLOCKS + G_BLOCKS - 1) / UTOT;
        const int slot = b - b_first;
        const int rowa = w*16 + tg, rowb = rowa + 8;
        const int pbase = (g*NSLOT + slot)*128;
        if (tc == 0) { g_pl[pbase + rowa] = lacc[0]; g_pl[pbase + rowb] = lacc[2]; }
        float2* pa  = (float2*)(g_po + ((size_t)(pbase + rowa))*DHEAD);
        float2* pbv = (float2*)(g_po + ((size_t)(pbase + rowb))*DHEAD);
        #pragma unroll
        for (int dt = 0; dt < 4; dt++) {
            pa [dt*4 + tc] = make_float2(oacc[dt][0], oacc[dt][1]);
            pbv[dt*4 + tc] = make_float2(oacc[dt][2], oacc[dt][3]);
        }
    };

    for (int u = ustart; u < uend; u++) {
        const int g = u / UPR;
        if (g != cg) {
            if (cg >= 0) flush(cg);
            cg = g;
            const int h = g / 50, qt = g % 50;
            const uint32_t* qb = (const uint32_t*)g_qs + ((size_t)h*LTOT + qt*128 + w*16)*16;
            #pragma unroll
            for (int ks = 0; ks < 2; ks++) {
                int ca = ks*8 + tc;
                qh[ks][0] = qb[tg*16     + ca];
                qh[ks][1] = qb[(tg+8)*16 + ca];
                qh[ks][2] = qb[tg*16     + ca + 4];
                qh[ks][3] = qb[(tg+8)*16 + ca + 4];
            }
            #pragma unroll
            for (int i = 0; i < 4; i++) {
                lacc[i] = 0.f;
                #pragma unroll
                for (int j = 0; j < 4; j++) oacc[i][j] = 0.f;
            }
        }

        if (u + 1 < uend) asm volatile("cp.async.wait_group 1;" ::: "memory");
        else              asm volatile("cp.async.wait_group 0;" ::: "memory");
        __syncthreads();

        const uint32_t kb = sbase + ((u - ustart) % NBUF)*BUFB;

        // ---- two 64-key halves behind one barrier ----
        #pragma unroll
        for (int s2 = 0; s2 < 2; s2++) {
            const uint32_t kK = kb + B_KH + s2*5120 + lmK;   // 64 rows x 80B per half
            const uint32_t kV = kb + B_VTH + s2*128 + lmV;   // 64-key column slice per half

            // S = Q K^T, accumulator pre-biased by SBIAS
            float sacc[8][4];
            #pragma unroll
            for (int nt = 0; nt < 8; nt++) {
                sacc[nt][0] = sacc[nt][1] = sacc[nt][2] = sacc[nt][3] = SBIAS;
                uint32_t bh[4];
                ldm_x4(bh, kK + nt*640);
                mma_f16(sacc[nt], qh[0], bh[0], bh[1]);
                mma_f16(sacc[nt], qh[1], bh[2], bh[3]);
            }

            // epilogue: p' = 2^(s-5) in f16x2; row-sum via ones-column GEMM
            uint32_t pha[4][4];
            #pragma unroll
            for (int kt2 = 0; kt2 < 4; kt2++) {
                pha[kt2][0] = ex2h2(packh(sacc[2*kt2][0],   sacc[2*kt2][1]));
                pha[kt2][1] = ex2h2(packh(sacc[2*kt2][2],   sacc[2*kt2][3]));
                pha[kt2][2] = ex2h2(packh(sacc[2*kt2+1][0], sacc[2*kt2+1][1]));
                pha[kt2][3] = ex2h2(packh(sacc[2*kt2+1][2], sacc[2*kt2+1][3]));
            }
            #pragma unroll
            for (int kt2 = 0; kt2 < 4; kt2++)
                mma_f16(lacc, pha[kt2], ones, ones);

            // O += P V
            #pragma unroll
            for (int dt = 0; dt < 4; dt++) {
                uint32_t vh[8];
                ldm_x4(vh,     kV + dt*2176);
                ldm_x4(vh + 4, kV + dt*2176 + 64);
                #pragma unroll
                for (int kt2 = 0; kt2 < 4; kt2++)
                    mma_f16(oacc[dt], pha[kt2], vh[2*kt2], vh[2*kt2+1]);
            }
        }

        // ---- prefetch unit u+2 into the buffer freed two iterations ago ----
        if (u + 2 < uend) load_unit(u + 2, (u - ustart + 2) % NBUF);
    }
    flush(cg);
}

// ---------------- kernel 4: fused slot-merge + overlap-average + proj conv + residual ----
// grid = 400 blocks x 256 thr: 4 pixels per block. Fixed-trip loops: all NSLOT
// slots are read unconditionally (unwritten slots are zero-init -> exact no-ops),
// and the 3x3 window walk is predicated, so all gather loads issue in parallel.
__global__ void final_kernel(const float* __restrict__ x,
                             const float* __restrict__ Wp, const float* __restrict__ bp,
                             const float* __restrict__ pa_p, float* __restrict__ out) {
    __shared__ __align__(16) float sg[4][68];
    int pl = threadIdx.x >> 6, c = threadIdx.x & 63;
    int p = blockIdx.x*4 + pl;
    int y = p / HW, xq = p % HW;
    int yp = y + 1, xp = xq + 1;
    int h = c >> 5, dd = c & 31;
    int sylo = yp - 3; if (sylo < 0) sylo = 0; sylo += (sylo & 1);
    int syhi = yp > 38 ? 38 : yp;  syhi -= (syhi & 1);
    int sxlo = xp - 3; if (sxlo < 0) sxlo = 0; sxlo += (sxlo & 1);
    int sxhi = xp > 38 ? 38 : xp;  sxhi -= (sxhi & 1);
    float acc = 0.f; int cnt = 0;
    #pragma unroll
    for (int ay = 0; ay < 3; ay++) {
        int sy = sylo + ay*2;
        #pragma unroll
        for (int ax = 0; ax < 3; ax++) {
            int sx = sxlo + ax*2;
            if (sy <= syhi && sx <= sxhi) {
                int ty = yp - sy, tx = xp - sx;
                int lw = ((sy >> 1)*NH + (sx >> 1))*NTOK + ty*4 + tx;
                int qt = lw >> 7, rowlocal = lw & 127;
                int base = ((h*50 + qt)*NSLOT)*128 + rowlocal;
                float l = 0.f, v = 0.f;
                #pragma unroll
                for (int s = 0; s < NSLOT; s++) {
                    l += g_pl[base + s*128];
                    v += g_po[(size_t)(base + s*128)*DHEAD + dd];
                }
                acc += __fdividef(v, l);
                cnt++;
            }
        }
    }
    sg[pl][c] = acc / ((float)cnt + 1e-6f);
    __syncthreads();
    float a = 2.f / (1.f + __expf(-(*pa_p)));
    float pr = bp[c];
    const float4* wrow = (const float4*)(Wp + c*64);
    #pragma unroll
    for (int i = 0; i < 16; i++) {
        float4 w = wrow[i];
        float4 g = *(const float4*)(&sg[pl][i*4]);
        pr += w.x*g.x + w.y*g.y + w.z*g.z + w.w*g.w;
    }
    int oi = c*1600 + y*HW + xq;
    out[oi] = x[oi] + a*pr;
}

// ---------------- launcher ----------------
extern "C" void kernel_launch(void* const* d_in, const int* in_sizes, int n_in,
                              void* d_out, int out_size) {
    (void)in_sizes; (void)n_in; (void)out_size;
    const float* x     = (const float*)d_in[0];
    const float* z     = (const float*)d_in[1];
    const float* Wqkv  = (const float*)d_in[2];
    const float* bqkv  = (const float*)d_in[3];
    const float* Wqkz  = (const float*)d_in[4];
    const float* bqkz  = (const float*)d_in[5];
    const float* Wproj = (const float*)d_in[6];
    const float* bproj = (const float*)d_in[7];
    const float* pa    = (const float*)d_in[8];
    const float* pbeta = (const float*)d_in[9];
    float* out = (float*)d_out;

    cudaFuncSetAttribute(flashmma_kernel, cudaFuncAttributeMaxDynamicSharedMemorySize, SMEM_FL);

    proj_kernel<<<dim3(HP, 4), 320>>>(x, z, Wqkv, bqkv, Wqkz, bqkz);
    local_attn_kernel<<<dim3(NWIN, HEADS), 256>>>(pbeta);
    flashmma_kernel<<<G_BLOCKS, 256, SMEM_FL>>>();
    final_kernel<<<HW*HW/4, 256>>>(x, Wproj, bproj, pa, out);
}